// round 8
// baseline (speedup 1.0000x reference)
#include <cuda_runtime.h>
#include <cuda_bf16.h>

#define MAX_RANKS (1 << 20)

__device__ int2  g_meta[MAX_RANKS];     // .x = count, .y = first index
__device__ int4  g_info[MAX_RANKS];     // {count, first, g_pred(-1 none), L_pred}
__device__ int   g_worklist[MAX_RANKS];
__device__ int   g_wcount;
__device__ int   g_maxrank;
__device__ int   g_done;
__device__ float g_T[256];

// hot region = output rows reachable by geom = c0 + c1*W + c2*H + c3
__device__ __forceinline__ long hot_bound(int B, int D, int H, int W, int C4, long n4) {
    long gmax = (long)(W - 1) + (long)(H - 1) * W + (long)(D - 1) * H + (B - 1);
    long hot = (gmax + 1) * C4;
    return hot < n4 ? hot : n4;
}

// ---------------------------------------------------------------- init: tables + cold-zero part A
__global__ void k_init(const int* __restrict__ Bp, const int* __restrict__ Dp,
                       const int* __restrict__ Hp, const int* __restrict__ Wp,
                       float4* __restrict__ out4z, long n4, int C4) {
    int stride = gridDim.x * blockDim.x;
    int t = blockIdx.x * blockDim.x + threadIdx.x;
    for (int i = t; i < MAX_RANKS; i += stride)
        g_meta[i] = make_int2(0, 0x7fffffff);
    long hot = hot_bound(*Bp, *Dp, *Hp, *Wp, C4, n4);
    long mid = hot + (n4 - hot) / 2;
    for (long z = hot + t; z < mid; z += stride)
        out4z[z] = make_float4(0.f, 0.f, 0.f, 0.f);
    if (t == 0) { g_maxrank = -1; g_wcount = 0; g_done = 0; }
    if (t < 256) g_T[t] = 0.0f;
}

// ---------------------------------------------------------------- pass A: histogram + cold-zero part B
__global__ void k_hist(const int4* __restrict__ coords, int N,
                       const int* __restrict__ Bp, const int* __restrict__ Dp,
                       const int* __restrict__ Hp, const int* __restrict__ Wp,
                       float4* __restrict__ out4z, long n4, int C4) {
    int i = blockIdx.x * blockDim.x + threadIdx.x;
    int B = *Bp, D = *Dp, H = *Hp, W = *Wp;

    long hot = hot_bound(B, D, H, W, C4, n4);
    long mid = hot + (n4 - hot) / 2;
    long zstride = (long)gridDim.x * blockDim.x;
    for (long z = mid + i; z < n4; z += zstride)
        out4z[z] = make_float4(0.f, 0.f, 0.f, 0.f);

    int s2 = B, s1 = D * B, s0 = W * s1;
    int myrank = -1;
    if (i < N) {
        int4 c = __ldcs(&coords[i]);
        int rank = c.x * s0 + c.y * s1 + c.z * s2 + c.w;
        myrank = rank;
        int old = atomicAdd(&g_meta[rank].x, 1);
        if (old == 0) {
            int pos = atomicAdd(&g_wcount, 1);
            g_worklist[pos] = rank;
        }
        atomicMin(&g_meta[rank].y, i);
    }
    __shared__ int sm[256];
    sm[threadIdx.x] = myrank;
    __syncthreads();
    for (int off = 128; off > 0; off >>= 1) {
        if (threadIdx.x < off) sm[threadIdx.x] = max(sm[threadIdx.x], sm[threadIdx.x + off]);
        __syncthreads();
    }
    if (threadIdx.x == 0) atomicMax(&g_maxrank, sm[0]);
}

// ---------------------------------------------------------------- prep: per-rank fused info + HOT zero (stays L2-resident)
__global__ void k_prep(const int* __restrict__ Bp, const int* __restrict__ Dp,
                       const int* __restrict__ Hp, const int* __restrict__ Wp,
                       float4* __restrict__ out4z, long n4, int C4) {
    int w = blockIdx.x * blockDim.x + threadIdx.x;
    int B = *Bp, D = *Dp, H = *Hp, W = *Wp;

    long hot = hot_bound(B, D, H, W, C4, n4);
    long zstride = (long)gridDim.x * blockDim.x;
    for (long z = w; z < hot; z += zstride)
        out4z[z] = make_float4(0.f, 0.f, 0.f, 0.f);

    if (w >= g_wcount) return;
    int j = g_worklist[w];

    int s2 = B, s1 = D * B, s0 = W * s1;
    int2 mj = g_meta[j];

    int p = j - 1;
    int Lp = 0;
    while (p >= 0) {
        Lp = g_meta[p].x;
        if (Lp != 0) break;
        p--;
    }
    int gp = -1;
    if (p >= 0) {
        int d0 = p / s0; int rr = p - d0 * s0;
        int d1 = rr / s1; rr -= d1 * s1;
        int d2 = rr / s2; int d3 = rr - d2 * s2;
        gp = d0 + d1 * W + d2 * H + d3;
    }
    g_info[j] = make_int4(mj.x, mj.y, gp, Lp);
}

// ---------------------------------------------------------------- main streaming pass (+ fused last-interval epilogue)
#define KB 16
#define ROWS (16 * KB)
__global__ void k_main(const float4* __restrict__ feats4, const int4* __restrict__ coords,
                       float4* __restrict__ out4, int N, int C4,
                       const int* __restrict__ Bp, const int* __restrict__ Dp,
                       const int* __restrict__ Hp, const int* __restrict__ Wp) {
    __shared__ int2   desc[ROWS];        // {target geom or -1, L}
    __shared__ float4 smr[16][64];
    __shared__ int    s_last;

    int tx = threadIdx.x;          // channel chunk (0..C4-1)
    int ty = threadIdx.y;          // row-in-tile (0..15)
    int lin = ty * C4 + tx;
    int base = blockIdx.x * ROWS;
    int maxr = g_maxrank;

    // ---- phase A: per-row metadata -> smem
    if (lin < ROWS) {
        int row = base + lin;
        int2 d = make_int2(-1, 0);
        if (row < N) {
            int B = *Bp, D = *Dp, H = *Hp, W = *Wp;
            int s2 = B, s1 = D * B, s0 = W * s1;
            int4 c = __ldcs(&coords[row]);
            int rank = c.x * s0 + c.y * s1 + c.z * s2 + c.w;
            int4 info = g_info[rank];
            if (row == info.y) {                 // first point of its rank
                if (info.z >= 0) d = make_int2(info.z, info.w);
            } else if (rank != maxr) {
                d = make_int2(c.x + c.y * W + c.z * H + c.w, info.x);
            }
        }
        desc[lin] = d;
    }
    __syncthreads();

    // ---- phase B: stream feats, accumulate T, fire atomics
    float4 tsum = make_float4(0.f, 0.f, 0.f, 0.f);
#pragma unroll
    for (int it = 0; it < KB; it++) {
        int r = it * 16 + ty;
        int row = base + r;
        if (row < N) {
            float4 v = __ldcs(&feats4[(long)row * C4 + tx]);
            tsum.x += v.x; tsum.y += v.y; tsum.z += v.z; tsum.w += v.w;
            int2 d = desc[r];
            if (d.x >= 0) {
                float L = (float)d.y;
                atomicAdd(&out4[(long)d.x * C4 + tx],
                          make_float4(L * v.x, L * v.y, L * v.z, L * v.w));
            }
        }
    }

    smr[ty][tx] = tsum;
    __syncthreads();
    if (ty == 0) {
        float4 a = smr[0][tx];
#pragma unroll
        for (int r = 1; r < 16; r++) {
            float4 b = smr[r][tx];
            a.x += b.x; a.y += b.y; a.z += b.z; a.w += b.w;
        }
        atomicAdd((float4*)&g_T[4 * tx], a);
    }

    // ---- fused k_last: last block to finish applies out[g_last] += L_last * T
    __threadfence();
    __syncthreads();
    if (lin == 0) {
        int t = atomicAdd(&g_done, 1);
        s_last = (t == gridDim.x - 1);
    }
    __syncthreads();
    if (s_last) {
        int m = maxr;
        if (m >= 0) {
            int B = *Bp, D = *Dp, H = *Hp, W = *Wp;
            int s2 = B, s1 = D * B, s0 = W * s1;
            int L = g_info[m].x;
            int c0 = m / s0; int r = m - c0 * s0;
            int c1 = r / s1; r -= c1 * s1;
            int c2 = r / s2; int c3 = r - c2 * s2;
            int g = c0 + c1 * W + c2 * H + c3;
            float* out = (float*)out4;
            int C = C4 * 4;
            for (int c = lin; c < C; c += C4 * 16) {
                float tv = __ldcg(&g_T[c]);
                atomicAdd(&out[(long)g * C + c], (float)L * tv);
            }
        }
    }
}

// ---------------------------------------------------------------- launch
extern "C" void kernel_launch(void* const* d_in, const int* in_sizes, int n_in,
                              void* d_out, int out_size) {
    const float* feats  = (const float*)d_in[0];
    const int*   coords = (const int*)d_in[1];
    const int*   Bp     = (const int*)d_in[2];
    const int*   Dp     = (const int*)d_in[3];
    const int*   Hp     = (const int*)d_in[4];
    const int*   Wp     = (const int*)d_in[5];

    int N  = in_sizes[1] / 4;
    int C  = in_sizes[0] / N;
    int C4 = C / 4;                 // C=80 -> 20

    int maxItems = N < MAX_RANKS ? N : MAX_RANKS;
    long n4 = (long)out_size / 4;

    k_init<<<2048, 512>>>(Bp, Dp, Hp, Wp, (float4*)d_out, n4, C4);
    k_hist<<<(N + 255) / 256, 256>>>((const int4*)coords, N, Bp, Dp, Hp, Wp,
                                     (float4*)d_out, n4, C4);
    k_prep<<<(maxItems + 255) / 256, 256>>>(Bp, Dp, Hp, Wp,
                                            (float4*)d_out, n4, C4);

    dim3 b2(C4, 16);
    k_main<<<(N + ROWS - 1) / ROWS, b2>>>(
        (const float4*)feats, (const int4*)coords, (float4*)d_out, N, C4, Bp, Dp, Hp, Wp);
}

// round 9
// speedup vs baseline: 1.1867x; 1.1867x over previous
#include <cuda_runtime.h>
#include <cuda_bf16.h>

#define MAX_RANKS (1 << 20)

__device__ int2  g_meta[MAX_RANKS];     // .x = count, .y = first index
__device__ int4  g_info[MAX_RANKS];     // {count, first, g_pred(-1 none), L_pred}
__device__ int   g_worklist[MAX_RANKS];
__device__ int   g_wcount;
__device__ int   g_maxrank;
__device__ float g_T[256];

// hot region = output rows reachable by geom = c0 + c1*W + c2*H + c3
__device__ __forceinline__ long hot_bound(int B, int D, int H, int W, int C4, long n4) {
    long gmax = (long)(W - 1) + (long)(H - 1) * W + (long)(D - 1) * H + (B - 1);
    long hot = (gmax + 1) * C4;
    return hot < n4 ? hot : n4;
}

// ---------------------------------------------------------------- init: tables + cold-zero part A (streaming stores)
__global__ void k_init(const int* __restrict__ Bp, const int* __restrict__ Dp,
                       const int* __restrict__ Hp, const int* __restrict__ Wp,
                       float4* __restrict__ out4z, long n4, int C4) {
    int stride = gridDim.x * blockDim.x;
    int t = blockIdx.x * blockDim.x + threadIdx.x;
    for (int i = t; i < MAX_RANKS; i += stride)
        g_meta[i] = make_int2(0, 0x7fffffff);
    long hot = hot_bound(*Bp, *Dp, *Hp, *Wp, C4, n4);
    long mid = hot + (n4 - hot) / 2;
    float4 zero = make_float4(0.f, 0.f, 0.f, 0.f);
    for (long z = hot + t; z < mid; z += stride)
        __stcs(&out4z[z], zero);
    if (t == 0) { g_maxrank = -1; g_wcount = 0; }
    if (t < 256) g_T[t] = 0.0f;
}

// ---------------------------------------------------------------- pass A: histogram + cold-zero part B (streaming stores)
__global__ void k_hist(const int4* __restrict__ coords, int N,
                       const int* __restrict__ Bp, const int* __restrict__ Dp,
                       const int* __restrict__ Hp, const int* __restrict__ Wp,
                       float4* __restrict__ out4z, long n4, int C4) {
    int i = blockIdx.x * blockDim.x + threadIdx.x;
    int B = *Bp, D = *Dp, H = *Hp, W = *Wp;

    long hot = hot_bound(B, D, H, W, C4, n4);
    long mid = hot + (n4 - hot) / 2;
    long zstride = (long)gridDim.x * blockDim.x;
    float4 zero = make_float4(0.f, 0.f, 0.f, 0.f);
    for (long z = mid + i; z < n4; z += zstride)
        __stcs(&out4z[z], zero);

    int s2 = B, s1 = D * B, s0 = W * s1;
    int myrank = -1;
    if (i < N) {
        int4 c = __ldcs(&coords[i]);
        int rank = c.x * s0 + c.y * s1 + c.z * s2 + c.w;
        myrank = rank;
        int old = atomicAdd(&g_meta[rank].x, 1);
        if (old == 0) {
            int pos = atomicAdd(&g_wcount, 1);
            g_worklist[pos] = rank;
        }
        atomicMin(&g_meta[rank].y, i);
    }
    __shared__ int sm[256];
    sm[threadIdx.x] = myrank;
    __syncthreads();
    for (int off = 128; off > 0; off >>= 1) {
        if (threadIdx.x < off) sm[threadIdx.x] = max(sm[threadIdx.x], sm[threadIdx.x + off]);
        __syncthreads();
    }
    if (threadIdx.x == 0) atomicMax(&g_maxrank, sm[0]);
}

// ---------------------------------------------------------------- prep: per-rank fused info + HOT zero (normal stores, L2-resident)
__global__ void k_prep(const int* __restrict__ Bp, const int* __restrict__ Dp,
                       const int* __restrict__ Hp, const int* __restrict__ Wp,
                       float4* __restrict__ out4z, long n4, int C4) {
    int w = blockIdx.x * blockDim.x + threadIdx.x;
    int B = *Bp, D = *Dp, H = *Hp, W = *Wp;

    long hot = hot_bound(B, D, H, W, C4, n4);
    long zstride = (long)gridDim.x * blockDim.x;
    for (long z = w; z < hot; z += zstride)
        out4z[z] = make_float4(0.f, 0.f, 0.f, 0.f);

    if (w >= g_wcount) return;
    int j = g_worklist[w];

    int s2 = B, s1 = D * B, s0 = W * s1;
    int2 mj = g_meta[j];

    int p = j - 1;
    int Lp = 0;
    while (p >= 0) {
        Lp = g_meta[p].x;
        if (Lp != 0) break;
        p--;
    }
    int gp = -1;
    if (p >= 0) {
        int d0 = p / s0; int rr = p - d0 * s0;
        int d1 = rr / s1; rr -= d1 * s1;
        int d2 = rr / s2; int d3 = rr - d2 * s2;
        gp = d0 + d1 * W + d2 * H + d3;
    }
    g_info[j] = make_int4(mj.x, mj.y, gp, Lp);
}

// ---------------------------------------------------------------- main streaming pass
#define KB 16
#define ROWS (16 * KB)
__global__ void k_main(const float4* __restrict__ feats4, const int4* __restrict__ coords,
                       float4* __restrict__ out4, int N, int C4,
                       const int* __restrict__ Bp, const int* __restrict__ Dp,
                       const int* __restrict__ Hp, const int* __restrict__ Wp) {
    __shared__ int2   desc[ROWS];        // {target geom or -1, L}
    __shared__ float4 smr[16][64];

    int tx = threadIdx.x;          // channel chunk (0..C4-1)
    int ty = threadIdx.y;          // row-in-tile (0..15)
    int lin = ty * C4 + tx;
    int base = blockIdx.x * ROWS;
    int maxr = g_maxrank;

    // ---- phase A: per-row metadata -> smem
    if (lin < ROWS) {
        int row = base + lin;
        int2 d = make_int2(-1, 0);
        if (row < N) {
            int B = *Bp, D = *Dp, H = *Hp, W = *Wp;
            int s2 = B, s1 = D * B, s0 = W * s1;
            int4 c = __ldcs(&coords[row]);
            int rank = c.x * s0 + c.y * s1 + c.z * s2 + c.w;
            int4 info = g_info[rank];
            if (row == info.y) {                 // first point of its rank
                if (info.z >= 0) d = make_int2(info.z, info.w);
            } else if (rank != maxr) {
                d = make_int2(c.x + c.y * W + c.z * H + c.w, info.x);
            }
        }
        desc[lin] = d;
    }
    __syncthreads();

    // ---- phase B: stream feats, accumulate T, fire atomics
    float4 tsum = make_float4(0.f, 0.f, 0.f, 0.f);
#pragma unroll
    for (int it = 0; it < KB; it++) {
        int r = it * 16 + ty;
        int row = base + r;
        if (row < N) {
            float4 v = __ldcs(&feats4[(long)row * C4 + tx]);
            tsum.x += v.x; tsum.y += v.y; tsum.z += v.z; tsum.w += v.w;
            int2 d = desc[r];
            if (d.x >= 0) {
                float L = (float)d.y;
                atomicAdd(&out4[(long)d.x * C4 + tx],
                          make_float4(L * v.x, L * v.y, L * v.z, L * v.w));
            }
        }
    }

    smr[ty][tx] = tsum;
    __syncthreads();
    if (ty == 0) {
        float4 a = smr[0][tx];
#pragma unroll
        for (int r = 1; r < 16; r++) {
            float4 b = smr[r][tx];
            a.x += b.x; a.y += b.y; a.z += b.z; a.w += b.w;
        }
        atomicAdd((float4*)&g_T[4 * tx], a);
    }
}

// ---------------------------------------------------------------- last interval: out[g_last] += L_last * T
__global__ void k_last(float* __restrict__ out, int C,
                       const int* __restrict__ Bp, const int* __restrict__ Dp,
                       const int* __restrict__ Hp, const int* __restrict__ Wp) {
    int m = g_maxrank;
    if (m < 0) return;
    int L = g_meta[m].x;
    int B = *Bp, D = *Dp, H = *Hp, W = *Wp;
    int s2 = B, s1 = D * B, s0 = W * s1;
    int c0 = m / s0; int r = m - c0 * s0;
    int c1 = r / s1; r -= c1 * s1;
    int c2 = r / s2; int c3 = r - c2 * s2;
    int g = c0 + c1 * W + c2 * H + c3;
    for (int c = threadIdx.x; c < C; c += blockDim.x)
        atomicAdd(&out[(long)g * C + c], (float)L * g_T[c]);
}

// ---------------------------------------------------------------- launch
extern "C" void kernel_launch(void* const* d_in, const int* in_sizes, int n_in,
                              void* d_out, int out_size) {
    const float* feats  = (const float*)d_in[0];
    const int*   coords = (const int*)d_in[1];
    const int*   Bp     = (const int*)d_in[2];
    const int*   Dp     = (const int*)d_in[3];
    const int*   Hp     = (const int*)d_in[4];
    const int*   Wp     = (const int*)d_in[5];

    int N  = in_sizes[1] / 4;
    int C  = in_sizes[0] / N;
    int C4 = C / 4;                 // C=80 -> 20

    int maxItems = N < MAX_RANKS ? N : MAX_RANKS;
    long n4 = (long)out_size / 4;

    k_init<<<2048, 512>>>(Bp, Dp, Hp, Wp, (float4*)d_out, n4, C4);
    k_hist<<<(N + 255) / 256, 256>>>((const int4*)coords, N, Bp, Dp, Hp, Wp,
                                     (float4*)d_out, n4, C4);
    k_prep<<<(maxItems + 255) / 256, 256>>>(Bp, Dp, Hp, Wp,
                                            (float4*)d_out, n4, C4);

    dim3 b2(C4, 16);
    k_main<<<(N + ROWS - 1) / ROWS, b2>>>(
        (const float4*)feats, (const int4*)coords, (float4*)d_out, N, C4, Bp, Dp, Hp, Wp);

    k_last<<<1, 256>>>((float*)d_out, C, Bp, Dp, Hp, Wp);
}